// round 15
// baseline (speedup 1.0000x reference)
#include <cuda_runtime.h>
#include <cuda_bf16.h>
#include <mma.h>
#include <cstdint>
#include <cstddef>

using namespace nvcuda;

#define R_TOT 8192      // B*T
#define FIN   512
#define DD    128
#define CH    32        // chunk length
#define NCHUNK 256      // R_TOT/CH
#define NC_B  64        // chunks per batch
#define AK    16
#define ASTRIDE 24
#define BSTRIDE 136
#define STAGE_BYTES 65536
#define PROJ_SMEM 50176   // 2x(128*24 + 128*24 + 16*136 + 16*136)*2B + 8KB scratch

// ---------------- static device scratch (no cudaMalloc allowed) -------------
__device__ __align__(16) __nv_bfloat16 gXh[R_TOT * FIN];
__device__ __align__(16) __nv_bfloat16 gXl[R_TOT * FIN];
__device__ __align__(16) __nv_bfloat16 gWh[4 * FIN * DD];
__device__ __align__(16) __nv_bfloat16 gWl[4 * FIN * DD];
__device__ __align__(16) float gK [R_TOT * DD];
__device__ __align__(16) float gQ [R_TOT * DD];
__device__ __align__(16) float gV [R_TOT * DD];
__device__ __align__(16) float gSC[R_TOT * DD];
__device__ __align__(16) float gP [R_TOT * DD];
__device__ __align__(16) float gSprev[NCHUNK * DD * DD];
__device__ __align__(16) float gZprev[NCHUNK * DD];

typedef unsigned long long u64;

__device__ __forceinline__ u64 pkdup(float v) {
    u64 r; asm("mov.b64 %0, {%1, %1};" : "=l"(r) : "f"(v)); return r;
}
__device__ __forceinline__ void fma2(u64& d, u64 a, u64 b) {
    asm("fma.rn.f32x2 %0, %1, %2, %0;" : "+l"(d) : "l"(a), "l"(b));
}
__device__ __forceinline__ float2 upk2(u64 v) {
    float lo, hi; asm("mov.b64 {%0, %1}, %2;" : "=f"(lo), "=f"(hi) : "l"(v));
    return make_float2(lo, hi);
}
__device__ __forceinline__ u64 pk2(float lo, float hi) {
    u64 r; asm("mov.b64 %0, {%1, %2};" : "=l"(r) : "f"(lo), "f"(hi)); return r;
}
__device__ __forceinline__ float phif(float z) { return z > 0.f ? z + 1.f : expf(z); }
__device__ __forceinline__ uint32_t smem_u32(const void* p) {
    uint32_t a;
    asm("{ .reg .u64 t; cvta.to.shared.u64 t, %1; cvt.u32.u64 %0, t; }" : "=r"(a) : "l"(p));
    return a;
}

// ---------------- 1) fused LayerNorm (bf16 hi/lo) + weight prep -------------
__global__ __launch_bounds__(128) void lnw_kernel(
    const float* __restrict__ h, const float* __restrict__ gam,
    const float* __restrict__ bet,
    const float* __restrict__ Wk, const float* __restrict__ Wq,
    const float* __restrict__ Wv, const float* __restrict__ Wsc) {
    int t = threadIdx.x;
    if (blockIdx.x >= R_TOT) {
        int idx = (blockIdx.x - R_TOT) * 128 + t;
        int y = idx >> 16;
        int rem = idx & 65535;
        const float* W = (y == 0) ? Wk : (y == 1) ? Wq : (y == 2) ? Wv : Wsc;
        float w = W[rem];
        __nv_bfloat16 hb = __float2bfloat16(w);
        __nv_bfloat16 lb = __float2bfloat16(w - __bfloat162float(hb));
        gWh[idx] = hb;
        gWl[idx] = lb;
        return;
    }
    int row = blockIdx.x;
    const float4* hr = reinterpret_cast<const float4*>(h + (size_t)row * FIN);
    float4 v = hr[t];
    float s = v.x + v.y + v.z + v.w;
    float s2 = v.x * v.x + v.y * v.y + v.z * v.z + v.w * v.w;
#pragma unroll
    for (int o = 16; o > 0; o >>= 1) {
        s  += __shfl_xor_sync(0xffffffffu, s,  o);
        s2 += __shfl_xor_sync(0xffffffffu, s2, o);
    }
    __shared__ float rs[4], rs2[4], bc[2];
    if ((t & 31) == 0) { rs[t >> 5] = s; rs2[t >> 5] = s2; }
    __syncthreads();
    if (t == 0) {
        float ss  = rs[0] + rs[1] + rs[2] + rs[3];
        float ss2 = rs2[0] + rs2[1] + rs2[2] + rs2[3];
        float mu  = ss * (1.0f / FIN);
        float var = ss2 * (1.0f / FIN) - mu * mu;
        bc[0] = mu; bc[1] = rsqrtf(var + 1e-5f);
    }
    __syncthreads();
    float mu = bc[0], rstd = bc[1];
    float4 g4 = reinterpret_cast<const float4*>(gam)[t];
    float4 b4 = reinterpret_cast<const float4*>(bet)[t];
    float o[4];
    o[0] = (v.x - mu) * rstd * g4.x + b4.x;
    o[1] = (v.y - mu) * rstd * g4.y + b4.y;
    o[2] = (v.z - mu) * rstd * g4.z + b4.z;
    o[3] = (v.w - mu) * rstd * g4.w + b4.w;
    unsigned short hs[4], ls[4];
#pragma unroll
    for (int i = 0; i < 4; i++) {
        __nv_bfloat16 hb = __float2bfloat16(o[i]);
        __nv_bfloat16 lb = __float2bfloat16(o[i] - __bfloat162float(hb));
        hs[i] = __bfloat16_as_ushort(hb);
        ls[i] = __bfloat16_as_ushort(lb);
    }
    size_t base = (size_t)row * FIN + t * 4;
    *(uint2*)&gXh[base] = make_uint2((uint32_t)hs[0] | ((uint32_t)hs[1] << 16),
                                     (uint32_t)hs[2] | ((uint32_t)hs[3] << 16));
    *(uint2*)&gXl[base] = make_uint2((uint32_t)ls[0] | ((uint32_t)ls[1] << 16),
                                     (uint32_t)ls[2] | ((uint32_t)ls[3] << 16));
}

// ---------------- 2) wmma bf16-split projection GEMM (ping-pong smem) -------
__global__ __launch_bounds__(256) void proj_mma_kernel(
    float* __restrict__ C0, float* __restrict__ C1,
    float* __restrict__ C2, float* __restrict__ C3) {
    extern __shared__ __align__(16) char pds[];
    __nv_bfloat16* AhB = (__nv_bfloat16*)pds;                 // 2 * 128*24
    __nv_bfloat16* AlB = AhB + 2 * 128 * ASTRIDE;
    __nv_bfloat16* BhB = AlB + 2 * 128 * ASTRIDE;             // 2 * 16*136
    __nv_bfloat16* BlB = BhB + 2 * AK * BSTRIDE;
    float* scratch = (float*)(BlB + 2 * AK * BSTRIDE);        // 8*256 fp32

    int tid = threadIdx.x, w = tid >> 5, lane = tid & 31;
    int y = blockIdx.y;
    int m0 = blockIdx.x * 128;
    const __nv_bfloat16* Ahg = gXh + (size_t)m0 * FIN;
    const __nv_bfloat16* Alg = gXl + (size_t)m0 * FIN;
    const __nv_bfloat16* Bhg = gWh + (size_t)y * FIN * DD;
    const __nv_bfloat16* Blg = gWl + (size_t)y * FIN * DD;

    int wm = w & 1, wn = w >> 1;

    wmma::fragment<wmma::accumulator, 16, 16, 16, float> acc[4][2];
#pragma unroll
    for (int i = 0; i < 4; i++)
#pragma unroll
        for (int j = 0; j < 2; j++) wmma::fill_fragment(acc[i][j], 0.0f);

    int arow = tid >> 1, ak = (tid & 1) * 8;
    int brow = tid >> 4, bcol = (tid & 15) * 8;

    uint4 pAh = *(const uint4*)&Ahg[(size_t)arow * FIN + ak];
    uint4 pAl = *(const uint4*)&Alg[(size_t)arow * FIN + ak];
    uint4 pBh = *(const uint4*)&Bhg[(size_t)brow * DD + bcol];
    uint4 pBl = *(const uint4*)&Blg[(size_t)brow * DD + bcol];

    int st = 0;
    for (int k0 = 0; k0 < FIN; k0 += AK, st ^= 1) {
        __nv_bfloat16* Ahs = AhB + st * (128 * ASTRIDE);
        __nv_bfloat16* Als = AlB + st * (128 * ASTRIDE);
        __nv_bfloat16* Bhs = BhB + st * (AK * BSTRIDE);
        __nv_bfloat16* Bls = BlB + st * (AK * BSTRIDE);
        *(uint4*)&Ahs[arow * ASTRIDE + ak]   = pAh;
        *(uint4*)&Als[arow * ASTRIDE + ak]   = pAl;
        *(uint4*)&Bhs[brow * BSTRIDE + bcol] = pBh;
        *(uint4*)&Bls[brow * BSTRIDE + bcol] = pBl;
        __syncthreads();
        if (k0 + AK < FIN) {
            pAh = *(const uint4*)&Ahg[(size_t)arow * FIN + k0 + AK + ak];
            pAl = *(const uint4*)&Alg[(size_t)arow * FIN + k0 + AK + ak];
            pBh = *(const uint4*)&Bhg[(size_t)(k0 + AK + brow) * DD + bcol];
            pBl = *(const uint4*)&Blg[(size_t)(k0 + AK + brow) * DD + bcol];
        }

        wmma::fragment<wmma::matrix_a, 16, 16, 16, __nv_bfloat16, wmma::row_major> fah[4], fal[4];
        wmma::fragment<wmma::matrix_b, 16, 16, 16, __nv_bfloat16, wmma::row_major> fbh[2], fbl[2];
#pragma unroll
        for (int i = 0; i < 4; i++) {
            wmma::load_matrix_sync(fah[i], &Ahs[(wm * 64 + i * 16) * ASTRIDE], ASTRIDE);
            wmma::load_matrix_sync(fal[i], &Als[(wm * 64 + i * 16) * ASTRIDE], ASTRIDE);
        }
#pragma unroll
        for (int j = 0; j < 2; j++) {
            wmma::load_matrix_sync(fbh[j], &Bhs[wn * 32 + j * 16], BSTRIDE);
            wmma::load_matrix_sync(fbl[j], &Bls[wn * 32 + j * 16], BSTRIDE);
        }
#pragma unroll
        for (int i = 0; i < 4; i++)
#pragma unroll
            for (int j = 0; j < 2; j++) {
                wmma::mma_sync(acc[i][j], fah[i], fbh[j], acc[i][j]);
                wmma::mma_sync(acc[i][j], fah[i], fbl[j], acc[i][j]);
                wmma::mma_sync(acc[i][j], fal[i], fbh[j], acc[i][j]);
            }
    }

    float* C = (y == 0) ? C0 : (y == 1) ? C1 : (y == 2) ? C2 : C3;
    bool dophi = (y < 2);
    int r = lane >> 1, c = (lane & 1) * 8;
    float* swr = scratch + w * 256;
#pragma unroll
    for (int i = 0; i < 4; i++)
#pragma unroll
        for (int j = 0; j < 2; j++) {
            wmma::store_matrix_sync(swr, acc[i][j], 16, wmma::mem_row_major);
            __syncwarp();
            float v[8];
#pragma unroll
            for (int e = 0; e < 8; e++) {
                v[e] = swr[r * 16 + c + e];
                if (dophi) v[e] = phif(v[e]);
            }
            int grow = m0 + wm * 64 + i * 16 + r;
            int gcol = wn * 32 + j * 16 + c;
            float* dst = C + (size_t)grow * DD + gcol;
            *(float4*)dst       = make_float4(v[0], v[1], v[2], v[3]);
            *(float4*)(dst + 4) = make_float4(v[4], v[5], v[6], v[7]);
            __syncwarp();
        }
}

// ---------------- 3) per-chunk KV outer-product sums + K sums ---------------
__global__ __launch_bounds__(256) void chunksum_kernel() {
    __shared__ float sK[CH][DD];
    __shared__ float sV[CH][DD];
    int tid = threadIdx.x;
    int chunk = blockIdx.x;
    int base = chunk * CH;
    int lr = tid >> 3, lc = (tid & 7) * 16;
#pragma unroll
    for (int j = 0; j < 4; j++) {
        *(float4*)&sK[lr][lc + 4 * j] = *(const float4*)&gK[(size_t)(base + lr) * DD + lc + 4 * j];
        *(float4*)&sV[lr][lc + 4 * j] = *(const float4*)&gV[(size_t)(base + lr) * DD + lc + 4 * j];
    }
    __syncthreads();

    int r0 = (tid >> 4) * 8;
    int c0 = (tid & 15) * 8;
    u64 acc[8][4];
#pragma unroll
    for (int i = 0; i < 8; i++)
#pragma unroll
        for (int j = 0; j < 4; j++) acc[i][j] = 0ull;

#pragma unroll 4
    for (int t = 0; t < CH; t++) {
        float4 kf0 = *(const float4*)&sK[t][r0];
        float4 kf1 = *(const float4*)&sK[t][r0 + 4];
        ulonglong2 v01 = *(const ulonglong2*)&sV[t][c0];
        ulonglong2 v23 = *(const ulonglong2*)&sV[t][c0 + 4];
        float kr[8] = {kf0.x, kf0.y, kf0.z, kf0.w, kf1.x, kf1.y, kf1.z, kf1.w};
#pragma unroll
        for (int i = 0; i < 8; i++) {
            u64 aa = pkdup(kr[i]);
            fma2(acc[i][0], aa, v01.x);
            fma2(acc[i][1], aa, v01.y);
            fma2(acc[i][2], aa, v23.x);
            fma2(acc[i][3], aa, v23.y);
        }
    }
    float* dst = gSprev + (size_t)chunk * DD * DD;
#pragma unroll
    for (int i = 0; i < 8; i++) {
        float2 f0 = upk2(acc[i][0]), f1 = upk2(acc[i][1]);
        float2 f2 = upk2(acc[i][2]), f3 = upk2(acc[i][3]);
        *(float4*)&dst[(r0 + i) * DD + c0]     = make_float4(f0.x, f0.y, f1.x, f1.y);
        *(float4*)&dst[(r0 + i) * DD + c0 + 4] = make_float4(f2.x, f2.y, f3.x, f3.y);
    }
    if (tid < DD) {
        float s = 0.f;
#pragma unroll 8
        for (int t = 0; t < CH; t++) s += sK[t][tid];
        gZprev[chunk * DD + tid] = s;
    }
}

// ---------------- 4) merged register-buffered exclusive scans ----------------
__global__ __launch_bounds__(256, 1) void scan_kernel(const float* __restrict__ S0,
                                                      const float* __restrict__ Z0) {
    if (blockIdx.y < 4) {
        int e = blockIdx.x * 256 + threadIdx.x;
        int b = blockIdx.y;
        float v[NC_B];
        size_t base = (size_t)b * NC_B * 16384 + e;
#pragma unroll
        for (int c = 0; c < NC_B; c++) v[c] = gSprev[base + (size_t)c * 16384];
        float run = S0[(size_t)b * 16384 + e];
#pragma unroll
        for (int c = 0; c < NC_B; c++) {
            float t = v[c];
            v[c] = run;
            run += t;
        }
#pragma unroll
        for (int c = 0; c < NC_B; c++) gSprev[base + (size_t)c * 16384] = v[c];
    } else if (blockIdx.x < 4 && threadIdx.x < DD) {
        int d = threadIdx.x;
        int b = blockIdx.x;
        float v[NC_B];
        size_t base = (size_t)b * NC_B * DD + d;
#pragma unroll
        for (int c = 0; c < NC_B; c++) v[c] = gZprev[base + (size_t)c * DD];
        float run = Z0[b * DD + d];
#pragma unroll
        for (int c = 0; c < NC_B; c++) {
            float t = v[c];
            v[c] = run;
            run += t;
        }
#pragma unroll
        for (int c = 0; c < NC_B; c++) gZprev[base + (size_t)c * DD] = v[c];
    }
}

// ---------------- 5) fused S-writer (TMA bulk) + attention -------------------
struct SwSM { float k[CH][DD]; float v[CH][DD]; };
struct AtSM {
    float q[CH][DD + 4];
    float kv[CH][DD + 4];
    float a[CH][CH + 2];
    float sp[16][DD];
    float row[CH];
    float zp[DD];
};

__global__ __launch_bounds__(512, 2) void swattn_kernel(float* __restrict__ Sout,
                                                        float* __restrict__ Zout) {
    extern __shared__ __align__(16) char dsm[];   // 64KB
    __shared__ SwSM sw;                           // 32KB static
    int tid = threadIdx.x;
    bool is_writer = blockIdx.x < NCHUNK;
    int chunk = is_writer ? blockIdx.x : (blockIdx.x - NCHUNK);
    int base = chunk * CH;

    if (is_writer) {
        int lr = tid >> 4, lc = (tid & 15) * 8;
        *(float4*)&sw.k[lr][lc]     = *(const float4*)&gK[(size_t)(base + lr) * DD + lc];
        *(float4*)&sw.k[lr][lc + 4] = *(const float4*)&gK[(size_t)(base + lr) * DD + lc + 4];
        *(float4*)&sw.v[lr][lc]     = *(const float4*)&gV[(size_t)(base + lr) * DD + lc];
        *(float4*)&sw.v[lr][lc + 4] = *(const float4*)&gV[(size_t)(base + lr) * DD + lc + 4];

        int r0 = (tid >> 4) * 4;
        int c0 = (tid & 15) * 8;
        const float* Sp = gSprev + (size_t)chunk * DD * DD;
        u64 acc[4][4];
#pragma unroll
        for (int i = 0; i < 4; i++) {
            float4 f0 = *(const float4*)&Sp[(r0 + i) * DD + c0];
            float4 f1 = *(const float4*)&Sp[(r0 + i) * DD + c0 + 4];
            acc[i][0] = pk2(f0.x, f0.y); acc[i][1] = pk2(f0.z, f0.w);
            acc[i][2] = pk2(f1.x, f1.y); acc[i][3] = pk2(f1.z, f1.w);
        }
        float* stage = (float*)dsm;
        uint32_t stage_u32 = smem_u32(dsm);
        __syncthreads();

        float4 kv = *(const float4*)&sw.k[0][r0];
        ulonglong2 v01 = *(const ulonglong2*)&sw.v[0][c0];
        ulonglong2 v23 = *(const ulonglong2*)&sw.v[0][c0 + 4];
        for (int t = 0; t < CH; t++) {
            int tn = (t + 1) & (CH - 1);
            float4 kvn = *(const float4*)&sw.k[tn][r0];
            ulonglong2 v01n = *(const ulonglong2*)&sw.v[tn][c0];
            ulonglong2 v23n = *(const ulonglong2*)&sw.v[tn][c0 + 4];
            float kr[4] = {kv.x, kv.y, kv.z, kv.w};
#pragma unroll
            for (int i = 0; i < 4; i++) {
                u64 aa = pkdup(kr[i]);
                fma2(acc[i][0], aa, v01.x);
                fma2(acc[i][1], aa, v01.y);
                fma2(acc[i][2], aa, v23.x);
                fma2(acc[i][3], aa, v23.y);
            }
            if (t > 0 && tid == 0)
                asm volatile("cp.async.bulk.wait_group.read 0;" ::: "memory");
            __syncthreads();
#pragma unroll
            for (int i = 0; i < 4; i++) {
                float2 f0 = upk2(acc[i][0]), f1 = upk2(acc[i][1]);
                float2 f2 = upk2(acc[i][2]), f3 = upk2(acc[i][3]);
                *(float4*)&stage[(r0 + i) * DD + c0]     = make_float4(f0.x, f0.y, f1.x, f1.y);
                *(float4*)&stage[(r0 + i) * DD + c0 + 4] = make_float4(f2.x, f2.y, f3.x, f3.y);
            }
            __syncthreads();
            if (tid == 0) {
                asm volatile("fence.proxy.async.shared::cta;" ::: "memory");
                asm volatile(
                    "cp.async.bulk.global.shared::cta.bulk_group [%0], [%1], %2;"
                    :: "l"(Sout + (size_t)(base + t) * 16384), "r"(stage_u32),
                       "r"((uint32_t)STAGE_BYTES) : "memory");
                asm volatile("cp.async.bulk.commit_group;" ::: "memory");
            }
            kv = kvn; v01 = v01n; v23 = v23n;
        }
        if (tid == 0)
            asm volatile("cp.async.bulk.wait_group 0;" ::: "memory");
    } else {
        AtSM& at = *reinterpret_cast<AtSM*>(dsm);
        int lr = tid >> 4, lc = (tid & 15) * 8;
        *(float4*)&at.q[lr][lc]      = *(const float4*)&gQ[(size_t)(base + lr) * DD + lc];
        *(float4*)&at.q[lr][lc + 4]  = *(const float4*)&gQ[(size_t)(base + lr) * DD + lc + 4];
        *(float4*)&at.kv[lr][lc]     = *(const float4*)&gK[(size_t)(base + lr) * DD + lc];
        *(float4*)&at.kv[lr][lc + 4] = *(const float4*)&gK[(size_t)(base + lr) * DD + lc + 4];
        if (tid < DD) at.zp[tid] = gZprev[chunk * DD + tid];
        __syncthreads();

        {
            int tq = tid >> 4;
            int tk = (tid & 15) * 2;
            u64 a2[2] = {0ull, 0ull};
#pragma unroll 8
            for (int dd = 0; dd < 64; dd++) {
                u64 qp  = *(const u64*)&at.q[tq][2 * dd];
                u64 kp0 = *(const u64*)&at.kv[tk][2 * dd];
                u64 kp1 = *(const u64*)&at.kv[tk + 1][2 * dd];
                fma2(a2[0], qp, kp0);
                fma2(a2[1], qp, kp1);
            }
#pragma unroll
            for (int j = 0; j < 2; j++) {
                float2 f = upk2(a2[j]);
                at.a[tq][tk + j] = (tk + j <= tq) ? (f.x + f.y) : 0.0f;
            }
        }

        if (tid < DD) {
            float zacc = at.zp[tid];
#pragma unroll 4
            for (int t = 0; t < CH; t++) {
                zacc += at.kv[t][tid];
                Zout[(size_t)(base + t) * DD + tid] = zacc;
            }
        }
        __syncthreads();

        if (tid < CH) {
            float s = 1e-5f;
#pragma unroll 8
            for (int c = 0; c < CH; c++) s += at.a[tid][c];
            float qz = 0.f;
#pragma unroll 8
            for (int d = 0; d < DD; d++) qz += at.q[tid][d] * at.zp[d];
            at.row[tid] = s + qz;
        }
        __syncthreads();

        *(float4*)&at.kv[lr][lc]     = *(const float4*)&gV[(size_t)(base + lr) * DD + lc];
        *(float4*)&at.kv[lr][lc + 4] = *(const float4*)&gV[(size_t)(base + lr) * DD + lc + 4];

        int r0 = tid >> 4;
        int c0 = (tid & 15) * 8;
        u64 acc[4] = {0ull, 0ull, 0ull, 0ull};

        const float* Sp = gSprev + (size_t)chunk * DD * DD;
        int spr = tid >> 5, spc = (tid & 31) * 4;
        float4 pf = *(const float4*)&Sp[(size_t)spr * DD + spc];
        for (int dt = 0; dt < 8; dt++) {
            __syncthreads();
            *(float4*)&at.sp[spr][spc] = pf;
            __syncthreads();
            if (dt < 7)
                pf = *(const float4*)&Sp[(size_t)((dt + 1) * 16 + spr) * DD + spc];
#pragma unroll
            for (int d = 0; d < 16; d++) {
                u64 aa = pkdup(at.q[r0][dt * 16 + d]);
                ulonglong2 s01 = *(const ulonglong2*)&at.sp[d][c0];
                ulonglong2 s23 = *(const ulonglong2*)&at.sp[d][c0 + 4];
                fma2(acc[0], aa, s01.x); fma2(acc[1], aa, s01.y);
                fma2(acc[2], aa, s23.x); fma2(acc[3], aa, s23.y);
            }
        }
        __syncthreads();

#pragma unroll 4
        for (int t = 0; t < CH; t++) {
            u64 aa = pkdup(at.a[r0][t]);
            ulonglong2 v01 = *(const ulonglong2*)&at.kv[t][c0];
            ulonglong2 v23 = *(const ulonglong2*)&at.kv[t][c0 + 4];
            fma2(acc[0], aa, v01.x); fma2(acc[1], aa, v01.y);
            fma2(acc[2], aa, v23.x); fma2(acc[3], aa, v23.y);
        }

        float rd = 1.0f / at.row[r0];
        float2 f0 = upk2(acc[0]), f1 = upk2(acc[1]);
        float2 f2 = upk2(acc[2]), f3 = upk2(acc[3]);
        float* dst = gP + (size_t)(base + r0) * DD + c0;
        *(float4*)dst       = make_float4(f0.x * rd, f0.y * rd, f1.x * rd, f1.y * rd);
        *(float4*)(dst + 4) = make_float4(f2.x * rd, f2.y * rd, f3.x * rd, f3.y * rd);
    }
}

// ---------------- 6) fused FF: O = relu(relu(P@w1+b1)@w2+b2) + SC + sc_b ----
__global__ __launch_bounds__(256) void ffboth_kernel(
    const float* __restrict__ P, const float* __restrict__ w1,
    const float* __restrict__ b1, const float* __restrict__ w2,
    const float* __restrict__ b2, const float* __restrict__ scb,
    const float* __restrict__ SC, float* __restrict__ O)
{
    __shared__ float As[16][68];
    __shared__ float Ws[16][132];
    __shared__ float Hs[64][132];

    int tid = threadIdx.x;
    int m0 = blockIdx.x * 64;
    int lrow = tid >> 2, lk = (tid & 3) * 4;
    int wrow = tid >> 4, wcol = (tid & 15) * 8;
    int r0 = (tid >> 4) * 4, c0 = (tid & 15) * 8;

    // ---- Phase 1: H = relu(P@w1 + b1) -> Hs ----
    u64 acc[4][4];
#pragma unroll
    for (int i = 0; i < 4; i++)
#pragma unroll
        for (int j = 0; j < 4; j++) acc[i][j] = 0ull;

    const float* aptr = P + (size_t)(m0 + lrow) * DD + lk;
    const float* wptr = w1 + (size_t)wrow * DD + wcol;

    float4 a0 = *(const float4*)(aptr);
    float4 w0 = *(const float4*)(wptr);
    float4 wv1 = *(const float4*)(wptr + 4);

    for (int k0 = 0; k0 < DD; k0 += 16) {
        __syncthreads();
        As[lk + 0][lrow] = a0.x; As[lk + 1][lrow] = a0.y;
        As[lk + 2][lrow] = a0.z; As[lk + 3][lrow] = a0.w;
        *(float4*)&Ws[wrow][wcol]     = w0;
        *(float4*)&Ws[wrow][wcol + 4] = wv1;
        __syncthreads();
        if (k0 + 16 < DD) {
            a0 = *(const float4*)(aptr + k0 + 16);
            w0 = *(const float4*)(wptr + (size_t)(k0 + 16) * DD);
            wv1 = *(const float4*)(wptr + (size_t)(k0 + 16) * DD + 4);
        }
#pragma unroll
        for (int kk = 0; kk < 16; kk++) {
            float4 af0 = *(const float4*)&As[kk][r0];
            ulonglong2 b01 = *(const ulonglong2*)&Ws[kk][c0];
            ulonglong2 b23 = *(const ulonglong2*)&Ws[kk][c0 + 4];
            float ar[4] = {af0.x, af0.y, af0.z, af0.w};
#pragma unroll
            for (int i = 0; i < 4; i++) {
                u64 aa = pkdup(ar[i]);
                fma2(acc[i][0], aa, b01.x);
                fma2(acc[i][1], aa, b01.y);
                fma2(acc[i][2], aa, b23.x);
                fma2(acc[i][3], aa, b23.y);
            }
        }
    }

    {
        float4 t0 = *(const float4*)&b1[c0], t1 = *(const float4*)&b1[c0 + 4];
        float bb[8] = {t0.x, t0.y, t0.z, t0.w, t1.x, t1.y, t1.z, t1.w};
#pragma unroll
        for (int i = 0; i < 4; i++) {
            float v[8];
#pragma unroll
            for (int j = 0; j < 4; j++) {
                float2 f = upk2(acc[i][j]);
                v[2 * j] = f.x; v[2 * j + 1] = f.y;
            }
#pragma unroll
            for (int x = 0; x < 8; x++) v[x] = fmaxf(v[x] + bb[x], 0.f);
            *(float4*)&Hs[r0 + i][c0]     = make_float4(v[0], v[1], v[2], v[3]);
            *(float4*)&Hs[r0 + i][c0 + 4] = make_float4(v[4], v[5], v[6], v[7]);
        }
    }
    __syncthreads();

    // ---- Phase 2: O = relu(H@w2 + b2) + SC + sc_b ----
#pragma unroll
    for (int i = 0; i < 4; i++)
#pragma unroll
        for (int j = 0; j < 4; j++) acc[i][j] = 0ull;

    const float* w2p = w2 + (size_t)wrow * DD + wcol;
    float4 u0 = *(const float4*)(w2p);
    float4 u1 = *(const float4*)(w2p + 4);

    for (int k0 = 0; k0 < DD; k0 += 16) {
        __syncthreads();
        *(float4*)&Ws[wrow][wcol]     = u0;
        *(float4*)&Ws[wrow][wcol + 4] = u1;
        __syncthreads();
        if (k0 + 16 < DD) {
            u0 = *(const float4*)(w2p + (size_t)(k0 + 16) * DD);
            u1 = *(const float4*)(w2p + (size_t)(k0 + 16) * DD + 4);
        }
#pragma unroll
        for (int kk = 0; kk < 16; kk++) {
            ulonglong2 b01 = *(const ulonglong2*)&Ws[kk][c0];
            ulonglong2 b23 = *(const ulonglong2*)&Ws[kk][c0 + 4];
#pragma unroll
            for (int i = 0; i < 4; i++) {
                u64 aa = pkdup(Hs[r0 + i][k0 + kk]);
                fma2(acc[i][0], aa, b01.x);
                fma2(acc[i][1], aa, b01.y);
                fma2(acc[i][2], aa, b23.x);
                fma2(acc[i][3], aa, b23.y);
            }
        }
    }

    {
        float4 t0 = *(const float4*)&b2[c0],  t1 = *(const float4*)&b2[c0 + 4];
        float4 s0 = *(const float4*)&scb[c0], s1 = *(const float4*)&scb[c0 + 4];
        float bb[8] = {t0.x, t0.y, t0.z, t0.w, t1.x, t1.y, t1.z, t1.w};
        float rb[8] = {s0.x, s0.y, s0.z, s0.w, s1.x, s1.y, s1.z, s1.w};
#pragma unroll
        for (int i = 0; i < 4; i++) {
            int row = m0 + r0 + i;
            float4 q0 = *(const float4*)&SC[(size_t)row * DD + c0];
            float4 q1 = *(const float4*)&SC[(size_t)row * DD + c0 + 4];
            float rr[8] = {q0.x, q0.y, q0.z, q0.w, q1.x, q1.y, q1.z, q1.w};
            float v[8];
#pragma unroll
            for (int j = 0; j < 4; j++) {
                float2 f = upk2(acc[i][j]);
                v[2 * j] = f.x; v[2 * j + 1] = f.y;
            }
#pragma unroll
            for (int x = 0; x < 8; x++) v[x] = fmaxf(v[x] + bb[x], 0.f) + rr[x] + rb[x];
            *(float4*)(O + (size_t)row * DD + c0)     = make_float4(v[0], v[1], v[2], v[3]);
            *(float4*)(O + (size_t)row * DD + c0 + 4) = make_float4(v[4], v[5], v[6], v[7]);
        }
    }
}

// ---------------- launch ------------------------------------------------------
extern "C" void kernel_launch(void* const* d_in, const int* in_sizes, int n_in,
                              void* d_out, int out_size) {
    const float* history = (const float*)d_in[0];
    const float* S0   = (const float*)d_in[1];
    const float* Z0   = (const float*)d_in[2];
    const float* Wk   = (const float*)d_in[3];
    const float* Wq   = (const float*)d_in[4];
    const float* Wv   = (const float*)d_in[5];
    const float* ln_g = (const float*)d_in[6];
    const float* ln_b = (const float*)d_in[7];
    const float* w1   = (const float*)d_in[8];
    const float* b1   = (const float*)d_in[9];
    const float* w2   = (const float*)d_in[10];
    const float* b2   = (const float*)d_in[11];
    const float* sc_w = (const float*)d_in[12];
    const float* sc_b = (const float*)d_in[13];

    float* outO = (float*)d_out;
    float* outS = outO + (size_t)R_TOT * DD;
    float* outZ = outS + (size_t)R_TOT * DD * DD;

    float *pK, *pQ, *pV, *pSC, *pP;
    cudaGetSymbolAddress((void**)&pK,  gK);
    cudaGetSymbolAddress((void**)&pQ,  gQ);
    cudaGetSymbolAddress((void**)&pV,  gV);
    cudaGetSymbolAddress((void**)&pSC, gSC);
    cudaGetSymbolAddress((void**)&pP,  gP);

    cudaFuncSetAttribute(swattn_kernel,
                         cudaFuncAttributeMaxDynamicSharedMemorySize, STAGE_BYTES);
    cudaFuncSetAttribute(proj_mma_kernel,
                         cudaFuncAttributeMaxDynamicSharedMemorySize, PROJ_SMEM);

    lnw_kernel<<<R_TOT + 2048, 128>>>(history, ln_g, ln_b, Wk, Wq, Wv, sc_w);
    proj_mma_kernel<<<dim3(64, 4), 256, PROJ_SMEM>>>(pK, pQ, pV, pSC);
    chunksum_kernel<<<NCHUNK, 256>>>();
    scan_kernel<<<dim3(64, 5), 256>>>(S0, Z0);
    swattn_kernel<<<2 * NCHUNK, 512, STAGE_BYTES>>>(outS, outZ);
    ffboth_kernel<<<128, 256>>>(pP, w1, b1, w2, b2, sc_b, pSC, outO);
}

// round 16
// speedup vs baseline: 1.0733x; 1.0733x over previous
#include <cuda_runtime.h>
#include <cuda_bf16.h>
#include <mma.h>
#include <cstdint>
#include <cstddef>

using namespace nvcuda;

#define R_TOT 8192      // B*T
#define FIN   512
#define DD    128
#define CH    32        // chunk length
#define NCHUNK 256      // R_TOT/CH
#define NC_B  64        // chunks per batch
#define AK    16
#define ASTRIDE 24
#define BSTRIDE 136
#define STAGE_BYTES 65536

// ---------------- static device scratch (no cudaMalloc allowed) -------------
__device__ __align__(16) __nv_bfloat16 gXh[R_TOT * FIN];
__device__ __align__(16) __nv_bfloat16 gXl[R_TOT * FIN];
__device__ __align__(16) __nv_bfloat16 gWh[4 * FIN * DD];
__device__ __align__(16) __nv_bfloat16 gWl[4 * FIN * DD];
__device__ __align__(16) float gK [R_TOT * DD];
__device__ __align__(16) float gQ [R_TOT * DD];
__device__ __align__(16) float gV [R_TOT * DD];
__device__ __align__(16) float gSC[R_TOT * DD];
__device__ __align__(16) float gP [R_TOT * DD];
__device__ __align__(16) float gH [R_TOT * DD];
__device__ __align__(16) float gSprev[NCHUNK * DD * DD];
__device__ __align__(16) float gZprev[NCHUNK * DD];

typedef unsigned long long u64;

__device__ __forceinline__ u64 pkdup(float v) {
    u64 r; asm("mov.b64 %0, {%1, %1};" : "=l"(r) : "f"(v)); return r;
}
__device__ __forceinline__ void fma2(u64& d, u64 a, u64 b) {
    asm("fma.rn.f32x2 %0, %1, %2, %0;" : "+l"(d) : "l"(a), "l"(b));
}
__device__ __forceinline__ float2 upk2(u64 v) {
    float lo, hi; asm("mov.b64 {%0, %1}, %2;" : "=f"(lo), "=f"(hi) : "l"(v));
    return make_float2(lo, hi);
}
__device__ __forceinline__ u64 pk2(float lo, float hi) {
    u64 r; asm("mov.b64 %0, {%1, %2};" : "=l"(r) : "f"(lo), "f"(hi)); return r;
}
__device__ __forceinline__ float phif(float z) { return z > 0.f ? z + 1.f : expf(z); }
__device__ __forceinline__ uint32_t smem_u32(const void* p) {
    uint32_t a;
    asm("{ .reg .u64 t; cvta.to.shared.u64 t, %1; cvt.u32.u64 %0, t; }" : "=r"(a) : "l"(p));
    return a;
}

// ---------------- 1) fused LayerNorm (bf16 hi/lo) + weight prep -------------
__global__ __launch_bounds__(128) void lnw_kernel(
    const float* __restrict__ h, const float* __restrict__ gam,
    const float* __restrict__ bet,
    const float* __restrict__ Wk, const float* __restrict__ Wq,
    const float* __restrict__ Wv, const float* __restrict__ Wsc) {
    int t = threadIdx.x;
    if (blockIdx.x >= R_TOT) {
        int idx = (blockIdx.x - R_TOT) * 128 + t;
        int y = idx >> 16;
        int rem = idx & 65535;
        const float* W = (y == 0) ? Wk : (y == 1) ? Wq : (y == 2) ? Wv : Wsc;
        float w = W[rem];
        __nv_bfloat16 hb = __float2bfloat16(w);
        __nv_bfloat16 lb = __float2bfloat16(w - __bfloat162float(hb));
        gWh[idx] = hb;
        gWl[idx] = lb;
        return;
    }
    int row = blockIdx.x;
    const float4* hr = reinterpret_cast<const float4*>(h + (size_t)row * FIN);
    float4 v = hr[t];
    float s = v.x + v.y + v.z + v.w;
    float s2 = v.x * v.x + v.y * v.y + v.z * v.z + v.w * v.w;
#pragma unroll
    for (int o = 16; o > 0; o >>= 1) {
        s  += __shfl_xor_sync(0xffffffffu, s,  o);
        s2 += __shfl_xor_sync(0xffffffffu, s2, o);
    }
    __shared__ float rs[4], rs2[4], bc[2];
    if ((t & 31) == 0) { rs[t >> 5] = s; rs2[t >> 5] = s2; }
    __syncthreads();
    if (t == 0) {
        float ss  = rs[0] + rs[1] + rs[2] + rs[3];
        float ss2 = rs2[0] + rs2[1] + rs2[2] + rs2[3];
        float mu  = ss * (1.0f / FIN);
        float var = ss2 * (1.0f / FIN) - mu * mu;
        bc[0] = mu; bc[1] = rsqrtf(var + 1e-5f);
    }
    __syncthreads();
    float mu = bc[0], rstd = bc[1];
    float4 g4 = reinterpret_cast<const float4*>(gam)[t];
    float4 b4 = reinterpret_cast<const float4*>(bet)[t];
    float o[4];
    o[0] = (v.x - mu) * rstd * g4.x + b4.x;
    o[1] = (v.y - mu) * rstd * g4.y + b4.y;
    o[2] = (v.z - mu) * rstd * g4.z + b4.z;
    o[3] = (v.w - mu) * rstd * g4.w + b4.w;
    unsigned short hs[4], ls[4];
#pragma unroll
    for (int i = 0; i < 4; i++) {
        __nv_bfloat16 hb = __float2bfloat16(o[i]);
        __nv_bfloat16 lb = __float2bfloat16(o[i] - __bfloat162float(hb));
        hs[i] = __bfloat16_as_ushort(hb);
        ls[i] = __bfloat16_as_ushort(lb);
    }
    size_t base = (size_t)row * FIN + t * 4;
    *(uint2*)&gXh[base] = make_uint2((uint32_t)hs[0] | ((uint32_t)hs[1] << 16),
                                     (uint32_t)hs[2] | ((uint32_t)hs[3] << 16));
    *(uint2*)&gXl[base] = make_uint2((uint32_t)ls[0] | ((uint32_t)ls[1] << 16),
                                     (uint32_t)ls[2] | ((uint32_t)ls[3] << 16));
}

// ---------------- 2) wmma bf16-split projection GEMM ------------------------
__global__ __launch_bounds__(256) void proj_mma_kernel(
    float* __restrict__ C0, float* __restrict__ C1,
    float* __restrict__ C2, float* __restrict__ C3) {
    __shared__ __nv_bfloat16 Ah[128][ASTRIDE];
    __shared__ __nv_bfloat16 Al[128][ASTRIDE];
    __shared__ __nv_bfloat16 Bh[AK][BSTRIDE];
    __shared__ __nv_bfloat16 Bl[AK][BSTRIDE];
    __shared__ float scratch[8][256];

    int tid = threadIdx.x, w = tid >> 5, lane = tid & 31;
    int y = blockIdx.y;
    int m0 = blockIdx.x * 128;
    const __nv_bfloat16* Ahg = gXh + (size_t)m0 * FIN;
    const __nv_bfloat16* Alg = gXl + (size_t)m0 * FIN;
    const __nv_bfloat16* Bhg = gWh + (size_t)y * FIN * DD;
    const __nv_bfloat16* Blg = gWl + (size_t)y * FIN * DD;

    int wm = w & 1, wn = w >> 1;

    wmma::fragment<wmma::accumulator, 16, 16, 16, float> acc[4][2];
#pragma unroll
    for (int i = 0; i < 4; i++)
#pragma unroll
        for (int j = 0; j < 2; j++) wmma::fill_fragment(acc[i][j], 0.0f);

    int arow = tid >> 1, ak = (tid & 1) * 8;
    int brow = tid >> 4, bcol = (tid & 15) * 8;

    uint4 pAh = *(const uint4*)&Ahg[(size_t)arow * FIN + ak];
    uint4 pAl = *(const uint4*)&Alg[(size_t)arow * FIN + ak];
    uint4 pBh = *(const uint4*)&Bhg[(size_t)brow * DD + bcol];
    uint4 pBl = *(const uint4*)&Blg[(size_t)brow * DD + bcol];

    for (int k0 = 0; k0 < FIN; k0 += AK) {
        __syncthreads();
        *(uint4*)&Ah[arow][ak]   = pAh;
        *(uint4*)&Al[arow][ak]   = pAl;
        *(uint4*)&Bh[brow][bcol] = pBh;
        *(uint4*)&Bl[brow][bcol] = pBl;
        __syncthreads();
        if (k0 + AK < FIN) {
            pAh = *(const uint4*)&Ahg[(size_t)arow * FIN + k0 + AK + ak];
            pAl = *(const uint4*)&Alg[(size_t)arow * FIN + k0 + AK + ak];
            pBh = *(const uint4*)&Bhg[(size_t)(k0 + AK + brow) * DD + bcol];
            pBl = *(const uint4*)&Blg[(size_t)(k0 + AK + brow) * DD + bcol];
        }

        wmma::fragment<wmma::matrix_a, 16, 16, 16, __nv_bfloat16, wmma::row_major> fah[4], fal[4];
        wmma::fragment<wmma::matrix_b, 16, 16, 16, __nv_bfloat16, wmma::row_major> fbh[2], fbl[2];
#pragma unroll
        for (int i = 0; i < 4; i++) {
            wmma::load_matrix_sync(fah[i], &Ah[wm * 64 + i * 16][0], ASTRIDE);
            wmma::load_matrix_sync(fal[i], &Al[wm * 64 + i * 16][0], ASTRIDE);
        }
#pragma unroll
        for (int j = 0; j < 2; j++) {
            wmma::load_matrix_sync(fbh[j], &Bh[0][wn * 32 + j * 16], BSTRIDE);
            wmma::load_matrix_sync(fbl[j], &Bl[0][wn * 32 + j * 16], BSTRIDE);
        }
#pragma unroll
        for (int i = 0; i < 4; i++)
#pragma unroll
            for (int j = 0; j < 2; j++) {
                wmma::mma_sync(acc[i][j], fah[i], fbh[j], acc[i][j]);
                wmma::mma_sync(acc[i][j], fah[i], fbl[j], acc[i][j]);
                wmma::mma_sync(acc[i][j], fal[i], fbh[j], acc[i][j]);
            }
    }

    float* C = (y == 0) ? C0 : (y == 1) ? C1 : (y == 2) ? C2 : C3;
    bool dophi = (y < 2);
    int r = lane >> 1, c = (lane & 1) * 8;
#pragma unroll
    for (int i = 0; i < 4; i++)
#pragma unroll
        for (int j = 0; j < 2; j++) {
            wmma::store_matrix_sync(&scratch[w][0], acc[i][j], 16, wmma::mem_row_major);
            __syncwarp();
            float v[8];
#pragma unroll
            for (int e = 0; e < 8; e++) {
                v[e] = scratch[w][r * 16 + c + e];
                if (dophi) v[e] = phif(v[e]);
            }
            int grow = m0 + wm * 64 + i * 16 + r;
            int gcol = wn * 32 + j * 16 + c;
            float* dst = C + (size_t)grow * DD + gcol;
            *(float4*)dst       = make_float4(v[0], v[1], v[2], v[3]);
            *(float4*)(dst + 4) = make_float4(v[4], v[5], v[6], v[7]);
            __syncwarp();
        }
}

// ---------------- 3) per-chunk KV outer-product sums + K sums ---------------
__global__ __launch_bounds__(256) void chunksum_kernel() {
    __shared__ float sK[CH][DD];
    __shared__ float sV[CH][DD];
    int tid = threadIdx.x;
    int chunk = blockIdx.x;
    int base = chunk * CH;
    int lr = tid >> 3, lc = (tid & 7) * 16;
#pragma unroll
    for (int j = 0; j < 4; j++) {
        *(float4*)&sK[lr][lc + 4 * j] = *(const float4*)&gK[(size_t)(base + lr) * DD + lc + 4 * j];
        *(float4*)&sV[lr][lc + 4 * j] = *(const float4*)&gV[(size_t)(base + lr) * DD + lc + 4 * j];
    }
    __syncthreads();

    int r0 = (tid >> 4) * 8;
    int c0 = (tid & 15) * 8;
    u64 acc[8][4];
#pragma unroll
    for (int i = 0; i < 8; i++)
#pragma unroll
        for (int j = 0; j < 4; j++) acc[i][j] = 0ull;

#pragma unroll 4
    for (int t = 0; t < CH; t++) {
        float4 kf0 = *(const float4*)&sK[t][r0];
        float4 kf1 = *(const float4*)&sK[t][r0 + 4];
        ulonglong2 v01 = *(const ulonglong2*)&sV[t][c0];
        ulonglong2 v23 = *(const ulonglong2*)&sV[t][c0 + 4];
        float kr[8] = {kf0.x, kf0.y, kf0.z, kf0.w, kf1.x, kf1.y, kf1.z, kf1.w};
#pragma unroll
        for (int i = 0; i < 8; i++) {
            u64 aa = pkdup(kr[i]);
            fma2(acc[i][0], aa, v01.x);
            fma2(acc[i][1], aa, v01.y);
            fma2(acc[i][2], aa, v23.x);
            fma2(acc[i][3], aa, v23.y);
        }
    }
    float* dst = gSprev + (size_t)chunk * DD * DD;
#pragma unroll
    for (int i = 0; i < 8; i++) {
        float2 f0 = upk2(acc[i][0]), f1 = upk2(acc[i][1]);
        float2 f2 = upk2(acc[i][2]), f3 = upk2(acc[i][3]);
        *(float4*)&dst[(r0 + i) * DD + c0]     = make_float4(f0.x, f0.y, f1.x, f1.y);
        *(float4*)&dst[(r0 + i) * DD + c0 + 4] = make_float4(f2.x, f2.y, f3.x, f3.y);
    }
    if (tid < DD) {
        float s = 0.f;
#pragma unroll 8
        for (int t = 0; t < CH; t++) s += sK[t][tid];
        gZprev[chunk * DD + tid] = s;
    }
}

// ---------------- 4) merged register-buffered exclusive scans ----------------
__global__ __launch_bounds__(256, 1) void scan_kernel(const float* __restrict__ S0,
                                                      const float* __restrict__ Z0) {
    if (blockIdx.y < 4) {
        int e = blockIdx.x * 256 + threadIdx.x;
        int b = blockIdx.y;
        float v[NC_B];
        size_t base = (size_t)b * NC_B * 16384 + e;
#pragma unroll
        for (int c = 0; c < NC_B; c++) v[c] = gSprev[base + (size_t)c * 16384];
        float run = S0[(size_t)b * 16384 + e];
#pragma unroll
        for (int c = 0; c < NC_B; c++) {
            float t = v[c];
            v[c] = run;
            run += t;
        }
#pragma unroll
        for (int c = 0; c < NC_B; c++) gSprev[base + (size_t)c * 16384] = v[c];
    } else if (blockIdx.x < 4 && threadIdx.x < DD) {
        int d = threadIdx.x;
        int b = blockIdx.x;
        float v[NC_B];
        size_t base = (size_t)b * NC_B * DD + d;
#pragma unroll
        for (int c = 0; c < NC_B; c++) v[c] = gZprev[base + (size_t)c * DD];
        float run = Z0[b * DD + d];
#pragma unroll
        for (int c = 0; c < NC_B; c++) {
            float t = v[c];
            v[c] = run;
            run += t;
        }
#pragma unroll
        for (int c = 0; c < NC_B; c++) gZprev[base + (size_t)c * DD] = v[c];
    }
}

// ---------------- FF GEMM ----------------------------------------------------
template<int MODE>
__global__ __launch_bounds__(256) void ff_kernel(
    const float* __restrict__ A, const float* __restrict__ W,
    float* __restrict__ C, const float* __restrict__ bias,
    const float* __restrict__ res, const float* __restrict__ resb)
{
    __shared__ float As[16][68];
    __shared__ float Ws[16][132];

    int tid = threadIdx.x;
    int m0 = blockIdx.x * 64;
    int lrow = tid >> 2, lk = (tid & 3) * 4;
    int wrow = tid >> 4, wcol = (tid & 15) * 8;
    int r0 = (tid >> 4) * 4, c0 = (tid & 15) * 8;

    u64 acc[4][4];
#pragma unroll
    for (int i = 0; i < 4; i++)
#pragma unroll
        for (int j = 0; j < 4; j++) acc[i][j] = 0ull;

    const float* aptr = A + (size_t)(m0 + lrow) * DD + lk;
    const float* wptr = W + (size_t)wrow * DD + wcol;

    float4 a0 = *(const float4*)(aptr);
    float4 w0 = *(const float4*)(wptr);
    float4 w1 = *(const float4*)(wptr + 4);

    for (int k0 = 0; k0 < DD; k0 += 16) {
        __syncthreads();
        As[lk + 0][lrow] = a0.x; As[lk + 1][lrow] = a0.y;
        As[lk + 2][lrow] = a0.z; As[lk + 3][lrow] = a0.w;
        *(float4*)&Ws[wrow][wcol]     = w0;
        *(float4*)&Ws[wrow][wcol + 4] = w1;
        __syncthreads();
        if (k0 + 16 < DD) {
            a0 = *(const float4*)(aptr + k0 + 16);
            w0 = *(const float4*)(wptr + (size_t)(k0 + 16) * DD);
            w1 = *(const float4*)(wptr + (size_t)(k0 + 16) * DD + 4);
        }
#pragma unroll
        for (int kk = 0; kk < 16; kk++) {
            float4 af0 = *(const float4*)&As[kk][r0];
            ulonglong2 b01 = *(const ulonglong2*)&Ws[kk][c0];
            ulonglong2 b23 = *(const ulonglong2*)&Ws[kk][c0 + 4];
            float ar[4] = {af0.x, af0.y, af0.z, af0.w};
#pragma unroll
            for (int i = 0; i < 4; i++) {
                u64 aa = pkdup(ar[i]);
                fma2(acc[i][0], aa, b01.x);
                fma2(acc[i][1], aa, b01.y);
                fma2(acc[i][2], aa, b23.x);
                fma2(acc[i][3], aa, b23.y);
            }
        }
    }

    float bb[8], rb[8];
    {
        float4 t0 = *(const float4*)&bias[c0], t1 = *(const float4*)&bias[c0 + 4];
        bb[0]=t0.x; bb[1]=t0.y; bb[2]=t0.z; bb[3]=t0.w;
        bb[4]=t1.x; bb[5]=t1.y; bb[6]=t1.z; bb[7]=t1.w;
    }
    if (MODE == 2) {
        float4 t0 = *(const float4*)&resb[c0], t1 = *(const float4*)&resb[c0 + 4];
        rb[0]=t0.x; rb[1]=t0.y; rb[2]=t0.z; rb[3]=t0.w;
        rb[4]=t1.x; rb[5]=t1.y; rb[6]=t1.z; rb[7]=t1.w;
    }
#pragma unroll
    for (int i = 0; i < 4; i++) {
        int row = m0 + r0 + i;
        float v[8];
#pragma unroll
        for (int j = 0; j < 4; j++) {
            float2 f = upk2(acc[i][j]);
            v[2 * j] = f.x; v[2 * j + 1] = f.y;
        }
        if (MODE == 1) {
#pragma unroll
            for (int x = 0; x < 8; x++) v[x] = fmaxf(v[x] + bb[x], 0.f);
        } else {
            float4 q0 = *(const float4*)&res[(size_t)row * DD + c0];
            float4 q1 = *(const float4*)&res[(size_t)row * DD + c0 + 4];
            float rr[8] = {q0.x, q0.y, q0.z, q0.w, q1.x, q1.y, q1.z, q1.w};
#pragma unroll
            for (int x = 0; x < 8; x++) v[x] = fmaxf(v[x] + bb[x], 0.f) + rr[x] + rb[x];
        }
        *(float4*)(C + (size_t)row * DD + c0)     = make_float4(v[0], v[1], v[2], v[3]);
        *(float4*)(C + (size_t)row * DD + c0 + 4) = make_float4(v[4], v[5], v[6], v[7]);
    }
}

// ---------------- 5) fused S-writer (TMA bulk) + attention -------------------
struct SwSM { float k[CH][DD]; float v[CH][DD]; };
struct AtSM {
    float q[CH][DD + 4];
    float kv[CH][DD + 4];
    float a[CH][CH + 2];
    float sp[16][DD];
    float row[CH];
    float zp[DD];
};

__global__ __launch_bounds__(512, 2) void swattn_kernel(float* __restrict__ Sout,
                                                        float* __restrict__ Zout) {
    extern __shared__ __align__(16) char dsm[];   // 64KB
    __shared__ SwSM sw;                           // 32KB static
    int tid = threadIdx.x;
    bool is_writer = blockIdx.x < NCHUNK;
    int chunk = is_writer ? blockIdx.x : (blockIdx.x - NCHUNK);
    int base = chunk * CH;

    if (is_writer) {
        int lr = tid >> 4, lc = (tid & 15) * 8;
        *(float4*)&sw.k[lr][lc]     = *(const float4*)&gK[(size_t)(base + lr) * DD + lc];
        *(float4*)&sw.k[lr][lc + 4] = *(const float4*)&gK[(size_t)(base + lr) * DD + lc + 4];
        *(float4*)&sw.v[lr][lc]     = *(const float4*)&gV[(size_t)(base + lr) * DD + lc];
        *(float4*)&sw.v[lr][lc + 4] = *(const float4*)&gV[(size_t)(base + lr) * DD + lc + 4];

        int r0 = (tid >> 4) * 4;
        int c0 = (tid & 15) * 8;
        const float* Sp = gSprev + (size_t)chunk * DD * DD;
        u64 acc[4][4];
#pragma unroll
        for (int i = 0; i < 4; i++) {
            float4 f0 = *(const float4*)&Sp[(r0 + i) * DD + c0];
            float4 f1 = *(const float4*)&Sp[(r0 + i) * DD + c0 + 4];
            acc[i][0] = pk2(f0.x, f0.y); acc[i][1] = pk2(f0.z, f0.w);
            acc[i][2] = pk2(f1.x, f1.y); acc[i][3] = pk2(f1.z, f1.w);
        }
        float* stage = (float*)dsm;
        uint32_t stage_u32 = smem_u32(dsm);
        __syncthreads();

        float4 kv = *(const float4*)&sw.k[0][r0];
        ulonglong2 v01 = *(const ulonglong2*)&sw.v[0][c0];
        ulonglong2 v23 = *(const ulonglong2*)&sw.v[0][c0 + 4];
        for (int t = 0; t < CH; t++) {
            int tn = (t + 1) & (CH - 1);
            float4 kvn = *(const float4*)&sw.k[tn][r0];
            ulonglong2 v01n = *(const ulonglong2*)&sw.v[tn][c0];
            ulonglong2 v23n = *(const ulonglong2*)&sw.v[tn][c0 + 4];
            float kr[4] = {kv.x, kv.y, kv.z, kv.w};
#pragma unroll
            for (int i = 0; i < 4; i++) {
                u64 aa = pkdup(kr[i]);
                fma2(acc[i][0], aa, v01.x);
                fma2(acc[i][1], aa, v01.y);
                fma2(acc[i][2], aa, v23.x);
                fma2(acc[i][3], aa, v23.y);
            }
            if (t > 0 && tid == 0)
                asm volatile("cp.async.bulk.wait_group.read 0;" ::: "memory");
            __syncthreads();
#pragma unroll
            for (int i = 0; i < 4; i++) {
                float2 f0 = upk2(acc[i][0]), f1 = upk2(acc[i][1]);
                float2 f2 = upk2(acc[i][2]), f3 = upk2(acc[i][3]);
                *(float4*)&stage[(r0 + i) * DD + c0]     = make_float4(f0.x, f0.y, f1.x, f1.y);
                *(float4*)&stage[(r0 + i) * DD + c0 + 4] = make_float4(f2.x, f2.y, f3.x, f3.y);
            }
            __syncthreads();
            if (tid == 0) {
                asm volatile("fence.proxy.async.shared::cta;" ::: "memory");
                asm volatile(
                    "cp.async.bulk.global.shared::cta.bulk_group [%0], [%1], %2;"
                    :: "l"(Sout + (size_t)(base + t) * 16384), "r"(stage_u32),
                       "r"((uint32_t)STAGE_BYTES) : "memory");
                asm volatile("cp.async.bulk.commit_group;" ::: "memory");
            }
            kv = kvn; v01 = v01n; v23 = v23n;
        }
        if (tid == 0)
            asm volatile("cp.async.bulk.wait_group 0;" ::: "memory");
    } else {
        AtSM& at = *reinterpret_cast<AtSM*>(dsm);
        int lr = tid >> 4, lc = (tid & 15) * 8;
        *(float4*)&at.q[lr][lc]      = *(const float4*)&gQ[(size_t)(base + lr) * DD + lc];
        *(float4*)&at.q[lr][lc + 4]  = *(const float4*)&gQ[(size_t)(base + lr) * DD + lc + 4];
        *(float4*)&at.kv[lr][lc]     = *(const float4*)&gK[(size_t)(base + lr) * DD + lc];
        *(float4*)&at.kv[lr][lc + 4] = *(const float4*)&gK[(size_t)(base + lr) * DD + lc + 4];
        if (tid < DD) at.zp[tid] = gZprev[chunk * DD + tid];
        __syncthreads();

        {
            int tq = tid >> 4;
            int tk = (tid & 15) * 2;
            u64 a2[2] = {0ull, 0ull};
#pragma unroll 8
            for (int dd = 0; dd < 64; dd++) {
                u64 qp  = *(const u64*)&at.q[tq][2 * dd];
                u64 kp0 = *(const u64*)&at.kv[tk][2 * dd];
                u64 kp1 = *(const u64*)&at.kv[tk + 1][2 * dd];
                fma2(a2[0], qp, kp0);
                fma2(a2[1], qp, kp1);
            }
#pragma unroll
            for (int j = 0; j < 2; j++) {
                float2 f = upk2(a2[j]);
                at.a[tq][tk + j] = (tk + j <= tq) ? (f.x + f.y) : 0.0f;
            }
        }

        if (tid < DD) {
            float zacc = at.zp[tid];
#pragma unroll 4
            for (int t = 0; t < CH; t++) {
                zacc += at.kv[t][tid];
                Zout[(size_t)(base + t) * DD + tid] = zacc;
            }
        }
        __syncthreads();

        if (tid < CH) {
            float s = 1e-5f;
#pragma unroll 8
            for (int c = 0; c < CH; c++) s += at.a[tid][c];
            float qz = 0.f;
#pragma unroll 8
            for (int d = 0; d < DD; d++) qz += at.q[tid][d] * at.zp[d];
            at.row[tid] = s + qz;
        }
        __syncthreads();

        *(float4*)&at.kv[lr][lc]     = *(const float4*)&gV[(size_t)(base + lr) * DD + lc];
        *(float4*)&at.kv[lr][lc + 4] = *(const float4*)&gV[(size_t)(base + lr) * DD + lc + 4];

        int r0 = tid >> 4;
        int c0 = (tid & 15) * 8;
        u64 acc[4] = {0ull, 0ull, 0ull, 0ull};

        const float* Sp = gSprev + (size_t)chunk * DD * DD;
        int spr = tid >> 5, spc = (tid & 31) * 4;
        float4 pf = *(const float4*)&Sp[(size_t)spr * DD + spc];
        for (int dt = 0; dt < 8; dt++) {
            __syncthreads();
            *(float4*)&at.sp[spr][spc] = pf;
            __syncthreads();
            if (dt < 7)
                pf = *(const float4*)&Sp[(size_t)((dt + 1) * 16 + spr) * DD + spc];
#pragma unroll
            for (int d = 0; d < 16; d++) {
                u64 aa = pkdup(at.q[r0][dt * 16 + d]);
                ulonglong2 s01 = *(const ulonglong2*)&at.sp[d][c0];
                ulonglong2 s23 = *(const ulonglong2*)&at.sp[d][c0 + 4];
                fma2(acc[0], aa, s01.x); fma2(acc[1], aa, s01.y);
                fma2(acc[2], aa, s23.x); fma2(acc[3], aa, s23.y);
            }
        }
        __syncthreads();

#pragma unroll 4
        for (int t = 0; t < CH; t++) {
            u64 aa = pkdup(at.a[r0][t]);
            ulonglong2 v01 = *(const ulonglong2*)&at.kv[t][c0];
            ulonglong2 v23 = *(const ulonglong2*)&at.kv[t][c0 + 4];
            fma2(acc[0], aa, v01.x); fma2(acc[1], aa, v01.y);
            fma2(acc[2], aa, v23.x); fma2(acc[3], aa, v23.y);
        }

        float rd = 1.0f / at.row[r0];
        float2 f0 = upk2(acc[0]), f1 = upk2(acc[1]);
        float2 f2 = upk2(acc[2]), f3 = upk2(acc[3]);
        float* dst = gP + (size_t)(base + r0) * DD + c0;
        *(float4*)dst       = make_float4(f0.x * rd, f0.y * rd, f1.x * rd, f1.y * rd);
        *(float4*)(dst + 4) = make_float4(f2.x * rd, f2.y * rd, f3.x * rd, f3.y * rd);
    }
}

// ---------------- launch ------------------------------------------------------
extern "C" void kernel_launch(void* const* d_in, const int* in_sizes, int n_in,
                              void* d_out, int out_size) {
    const float* history = (const float*)d_in[0];
    const float* S0   = (const float*)d_in[1];
    const float* Z0   = (const float*)d_in[2];
    const float* Wk   = (const float*)d_in[3];
    const float* Wq   = (const float*)d_in[4];
    const float* Wv   = (const float*)d_in[5];
    const float* ln_g = (const float*)d_in[6];
    const float* ln_b = (const float*)d_in[7];
    const float* w1   = (const float*)d_in[8];
    const float* b1   = (const float*)d_in[9];
    const float* w2   = (const float*)d_in[10];
    const float* b2   = (const float*)d_in[11];
    const float* sc_w = (const float*)d_in[12];
    const float* sc_b = (const float*)d_in[13];

    float* outO = (float*)d_out;
    float* outS = outO + (size_t)R_TOT * DD;
    float* outZ = outS + (size_t)R_TOT * DD * DD;

    float *pK, *pQ, *pV, *pSC, *pP, *pH;
    cudaGetSymbolAddress((void**)&pK,  gK);
    cudaGetSymbolAddress((void**)&pQ,  gQ);
    cudaGetSymbolAddress((void**)&pV,  gV);
    cudaGetSymbolAddress((void**)&pSC, gSC);
    cudaGetSymbolAddress((void**)&pP,  gP);
    cudaGetSymbolAddress((void**)&pH,  gH);

    cudaFuncSetAttribute(swattn_kernel,
                         cudaFuncAttributeMaxDynamicSharedMemorySize, STAGE_BYTES);

    lnw_kernel<<<R_TOT + 2048, 128>>>(history, ln_g, ln_b, Wk, Wq, Wv, sc_w);
    proj_mma_kernel<<<dim3(64, 4), 256>>>(pK, pQ, pV, pSC);
    chunksum_kernel<<<NCHUNK, 256>>>();
    scan_kernel<<<dim3(64, 5), 256>>>(S0, Z0);
    swattn_kernel<<<2 * NCHUNK, 512, STAGE_BYTES>>>(outS, outZ);
    ff_kernel<1><<<128, 256>>>(pP, w1, pH, b1, nullptr, nullptr);
    ff_kernel<2><<<128, 256>>>(pH, w2, outO, b2, pSC, sc_b);
}